// round 17
// baseline (speedup 1.0000x reference)
#include <cuda_runtime.h>
#include <cuda_fp16.h>
#include <cstdint>

#define NELEM 16777216            // 4*16*2048*128

// ---------------- global scratch (allocation-free) ----------------
__device__ __align__(16) uint32_t g_mask[2048 * 64];
__device__ __align__(16) __half g_qh[NELEM];
__device__ __align__(16) __half g_kh[NELEM];
__device__ __align__(16) __half g_vh[NELEM];

// ---------------- smem: persistent Q (128 rows) + 4-buffer K/V ring (64-row tiles)
#define ROWB 272                  // padded row stride in bytes (136 halves)
#define QBUF_B (128 * ROWB)       // 34816
#define KVB    (64 * ROWB)        // 17408 per 64x128 tile
#define SMEM_B (QBUF_B + 4 * KVB) // 104448 -> 2 CTAs/SM

// ---------------- helpers ----------------
__device__ __forceinline__ uint32_t smem_u32(const void* p) {
    uint32_t a;
    asm("{ .reg .u64 t; cvta.to.shared.u64 t, %1; cvt.u32.u64 %0, t; }" : "=r"(a) : "l"(p));
    return a;
}
__device__ __forceinline__ float ex2(float x) {
    float y; asm("ex2.approx.ftz.f32 %0, %1;" : "=f"(y) : "f"(x)); return y;
}
__device__ __forceinline__ uint32_t packh2(float x0, float x1) {
    __half2 h = __floats2half2_rn(x0, x1);
    return *reinterpret_cast<uint32_t*>(&h);
}
__device__ __forceinline__ void mma_f16(float* c, const uint32_t* a, const uint32_t* b) {
    asm volatile("mma.sync.aligned.m16n8k16.row.col.f32.f16.f16.f32 "
        "{%0,%1,%2,%3}, {%4,%5,%6,%7}, {%8,%9}, {%0,%1,%2,%3};"
        : "+f"(c[0]), "+f"(c[1]), "+f"(c[2]), "+f"(c[3])
        : "r"(a[0]), "r"(a[1]), "r"(a[2]), "r"(a[3]), "r"(b[0]), "r"(b[1]));
}
#define LDSM_X4(r, addr) \
    asm volatile("ldmatrix.sync.aligned.m8n8.x4.shared.b16 {%0,%1,%2,%3}, [%4];" \
        : "=r"((r)[0]), "=r"((r)[1]), "=r"((r)[2]), "=r"((r)[3]) : "r"(addr))
#define LDSM_X4T(r, addr) \
    asm volatile("ldmatrix.sync.aligned.m8n8.x4.trans.shared.b16 {%0,%1,%2,%3}, [%4];" \
        : "=r"((r)[0]), "=r"((r)[1]), "=r"((r)[2]), "=r"((r)[3]) : "r"(addr))
__device__ __forceinline__ void cpa16(uint32_t dst, const void* src) {
    asm volatile("cp.async.cg.shared.global [%0], [%1], 16;" :: "r"(dst), "l"(src) : "memory");
}
#define CP_COMMIT() asm volatile("cp.async.commit_group;" ::: "memory")
#define CP_WAIT(n)  asm volatile("cp.async.wait_group %0;" :: "n"(n) : "memory")

// padded byte offset for data uint4 index i (row = i>>4, col16 = i&15)
__device__ __forceinline__ uint32_t pad_off(int i) {
    return (uint32_t)(((i >> 4) * 17 + (i & 15)) * 16);
}

// ---------------- prep kernels ----------------
__global__ void pack_mask_kernel(const int* __restrict__ mask) {
    int w = blockIdx.x * blockDim.x + threadIdx.x;
    const int4* m4 = reinterpret_cast<const int4*>(mask) + (size_t)w * 8;
    uint32_t b = 0;
#pragma unroll
    for (int i = 0; i < 8; i++) {
        int4 v = m4[i];
        b |= (uint32_t)(v.x != 0) << (i * 4)     | (uint32_t)(v.y != 0) << (i * 4 + 1)
           | (uint32_t)(v.z != 0) << (i * 4 + 2) | (uint32_t)(v.w != 0) << (i * 4 + 3);
    }
    g_mask[w] = b;
}
__global__ void prep_q_kernel(const float4* __restrict__ q) {
    const float CS = 1.4426950408889634f / 11.313708498984761f;  // log2(e)/sqrt(128)
    int i = blockIdx.x * 256 + threadIdx.x;
    float4 x = q[i];
    reinterpret_cast<uint2*>(g_qh)[i] = make_uint2(packh2(x.x * CS, x.y * CS),
                                                   packh2(x.z * CS, x.w * CS));
}
__global__ void prep_kv_kernel(const float4* __restrict__ k, const float4* __restrict__ v) {
    int i = blockIdx.x * 256 + threadIdx.x;
    const float4* src = blockIdx.y ? v : k;
    __half* dst = blockIdx.y ? g_vh : g_kh;
    float4 x = src[i];
    reinterpret_cast<uint2*>(dst)[i] = make_uint2(packh2(x.x, x.y), packh2(x.z, x.w));
}

// ---------------- main kernel: grid(16, 64), 128 threads (4 warps x 32 rows) ------
__global__ void __launch_bounds__(128, 2)
flash_mma_kernel(float* __restrict__ Out)
{
    extern __shared__ __align__(16) char smp[];
    const uint32_t sbase = smem_u32(smp);
    const int tid = threadIdx.x, w = tid >> 5, lane = tid & 31;
    const int bh = blockIdx.y, qb = blockIdx.x;

    const size_t KV4 = 1024;                            // uint4 per 64x128 fp16 tile
    const size_t hbase4 = (size_t)bh * (KV4 * 32);      // 32 k-tiles per head
    const size_t qtile4 = (size_t)bh * 32768 + (size_t)qb * 2048;  // 128 Q rows

    const uint4* gq4 = reinterpret_cast<const uint4*>(g_qh);
    const uint4* gk4 = reinterpret_cast<const uint4*>(g_kh);
    const uint4* gv4 = reinterpret_cast<const uint4*>(g_vh);

    // ---- prologue: G0 = {Q, K0, V0} ; G1 = {K1, V1} ----
    for (int i = tid; i < 2048; i += 128)
        cpa16(sbase + pad_off(i), gq4 + qtile4 + i);
    for (int i = tid; i < 1024; i += 128) {
        uint32_t po = pad_off(i);
        cpa16(sbase + QBUF_B + 0 * KVB + po, gk4 + hbase4 + i);
        cpa16(sbase + QBUF_B + 1 * KVB + po, gv4 + hbase4 + i);
    }
    CP_COMMIT();
    for (int i = tid; i < 1024; i += 128) {
        uint32_t po = pad_off(i);
        cpa16(sbase + QBUF_B + 2 * KVB + po, gk4 + hbase4 + KV4 + i);
        cpa16(sbase + QBUF_B + 3 * KVB + po, gv4 + hbase4 + KV4 + i);
    }
    CP_COMMIT();

    float oacc[2][16][4];
    float lsum0[2], lsum1[2];
#pragma unroll
    for (int mt = 0; mt < 2; mt++) {
        lsum0[mt] = lsum1[mt] = 0.f;
#pragma unroll
        for (int i = 0; i < 16; i++)
            oacc[mt][i][0] = oacc[mt][i][1] = oacc[mt][i][2] = oacc[mt][i][3] = 0.f;
    }

    // per-thread ldmatrix base byte addresses
    const uint32_t aQ0 = sbase + (w * 32 + (lane & 15)) * ROWB + ((lane & 16) ? 16 : 0);
    const uint32_t bK  = ((lane >> 4) * 8 + (lane & 7)) * ROWB + ((lane & 8) ? 16 : 0);
    const uint32_t vVb = (lane & 15) * ROWB + ((lane >> 4) ? 16 : 0);

    const int shf = (lane & 3) * 2;
    const int r0 = w * 32 + (lane >> 2);                // mt=0 base row (local)
    const uint32_t* mbase = g_mask + (size_t)(qb * 128) * 64;

#pragma unroll 1
    for (int t = 0; t < 32; t++) {
        if (t == 31) { CP_WAIT(0); } else { CP_WAIT(1); }
        __syncthreads();    // K(t)/V(t) visible to all warps

        const uint32_t kcur = sbase + QBUF_B + (uint32_t)(2 * (t & 1)) * KVB;
        const uint32_t vcur = kcur + KVB;

        // ---- mask words (registers, reused across chunks) ----
        uint32_t mq[2][2][2];   // [mt][rowhalf][word]
#pragma unroll
        for (int mt = 0; mt < 2; mt++) {
            const int ra = r0 + 16 * mt;
            mq[mt][0][0] = __ldg(mbase + (size_t)ra * 64 + t * 2);
            mq[mt][0][1] = __ldg(mbase + (size_t)ra * 64 + t * 2 + 1);
            mq[mt][1][0] = __ldg(mbase + (size_t)(ra + 8) * 64 + t * 2);
            mq[mt][1][1] = __ldg(mbase + (size_t)(ra + 8) * 64 + t * 2 + 1);
        }

        // ---- per 32-key chunk: S -> convert -> PV (sacc only 32 regs live) ----
#pragma unroll
        for (int nc = 0; nc < 2; nc++) {
            float sacc[2][4][4];
#pragma unroll
            for (int mt = 0; mt < 2; mt++)
#pragma unroll
                for (int j = 0; j < 4; j++)
                    sacc[mt][j][0] = sacc[mt][j][1] = sacc[mt][j][2] = sacc[mt][j][3] = 0.f;

            // S-phase for keys [32nc, 32nc+32): Q reloaded per chunk (conflict-free LDSM)
#pragma unroll
            for (int kt = 0; kt < 8; kt++) {
                uint32_t Qa[2][4];
                LDSM_X4(Qa[0], aQ0 + kt * 32);
                LDSM_X4(Qa[1], aQ0 + 16 * ROWB + kt * 32);
#pragma unroll
                for (int jS = 0; jS < 2; jS++) {
                    uint32_t Bk[4];
                    LDSM_X4(Bk, kcur + bK + (nc * 2 + jS) * (16 * ROWB) + kt * 32);
                    mma_f16(sacc[0][2 * jS],     Qa[0], Bk);
                    mma_f16(sacc[0][2 * jS + 1], Qa[0], Bk + 2);
                    mma_f16(sacc[1][2 * jS],     Qa[1], Bk);
                    mma_f16(sacc[1][2 * jS + 1], Qa[1], Bk + 2);
                }
            }

            // convert + PV for the two 16-key subchunks of this 32-key chunk
#pragma unroll
            for (int kt2 = 0; kt2 < 2; kt2++) {
                uint32_t AHc[2][4];
#pragma unroll
                for (int mt = 0; mt < 2; mt++) {
                    const int n0 = nc * 4 + 2 * kt2, n1 = n0 + 1;   // 8-key group idx in tile
                    const int j0 = 2 * kt2, j1 = 2 * kt2 + 1;       // sacc j idx
                    uint32_t a0 = mq[mt][0][n0 >> 2] >> ((n0 & 3) * 8 + shf);
                    uint32_t a1 = mq[mt][1][n0 >> 2] >> ((n0 & 3) * 8 + shf);
                    uint32_t c0 = mq[mt][0][n1 >> 2] >> ((n1 & 3) * 8 + shf);
                    uint32_t c1 = mq[mt][1][n1 >> 2] >> ((n1 & 3) * 8 + shf);
                    float p0 = (a0 & 1u) ? ex2(sacc[mt][j0][0]) : 0.f;
                    float p1 = (a0 & 2u) ? ex2(sacc[mt][j0][1]) : 0.f;
                    float p2 = (a1 & 1u) ? ex2(sacc[mt][j0][2]) : 0.f;
                    float p3 = (a1 & 2u) ? ex2(sacc[mt][j0][3]) : 0.f;
                    float p4 = (c0 & 1u) ? ex2(sacc[mt][j1][0]) : 0.f;
                    float p5 = (c0 & 2u) ? ex2(sacc[mt][j1][1]) : 0.f;
                    float p6 = (c1 & 1u) ? ex2(sacc[mt][j1][2]) : 0.f;
                    float p7 = (c1 & 2u) ? ex2(sacc[mt][j1][3]) : 0.f;
                    lsum0[mt] += (p0 + p1) + (p4 + p5);
                    lsum1[mt] += (p2 + p3) + (p6 + p7);
                    AHc[mt][0] = packh2(p0, p1);
                    AHc[mt][1] = packh2(p2, p3);
                    AHc[mt][2] = packh2(p4, p5);
                    AHc[mt][3] = packh2(p6, p7);
                }
#pragma unroll
                for (int jV = 0; jV < 8; jV++) {
                    uint32_t Bv[4];
                    LDSM_X4T(Bv, vcur + vVb + (nc * 2 + kt2) * (16 * ROWB) + jV * 32);
                    mma_f16(oacc[0][2 * jV],     AHc[0], Bv);
                    mma_f16(oacc[0][2 * jV + 1], AHc[0], Bv + 2);
                    mma_f16(oacc[1][2 * jV],     AHc[1], Bv);
                    mma_f16(oacc[1][2 * jV + 1], AHc[1], Bv + 2);
                }
            }
        }

        __syncthreads();    // all warps done reading K(t)/V(t) before ring reuse
        if (t + 2 < 32) {   // prefetch K/V(t+2) into the buffers just freed
            const size_t toff = hbase4 + (size_t)(t + 2) * KV4;
            for (int i = tid; i < 1024; i += 128) {
                uint32_t po = pad_off(i);
                cpa16(kcur + po, gk4 + toff + i);
                cpa16(vcur + po, gv4 + toff + i);
            }
            CP_COMMIT();
        }
    }

    // ---- epilogue: quad-reduce row sums, normalize, store ----
    const size_t hbase = (size_t)bh * 262144;
#pragma unroll
    for (int mt = 0; mt < 2; mt++) {
        float s0 = lsum0[mt], s1 = lsum1[mt];
        s0 += __shfl_xor_sync(0xffffffffu, s0, 1);
        s0 += __shfl_xor_sync(0xffffffffu, s0, 2);
        s1 += __shfl_xor_sync(0xffffffffu, s1, 1);
        s1 += __shfl_xor_sync(0xffffffffu, s1, 2);
        float inv0 = 1.f / s0, inv1 = 1.f / s1;
        const int grow = qb * 128 + r0 + 16 * mt;
        float* p0 = Out + hbase + (size_t)grow * 128 + (lane & 3) * 2;
        float* p1 = p0 + 8 * 128;
#pragma unroll
        for (int dt = 0; dt < 16; dt++) {
            *reinterpret_cast<float2*>(p0 + dt * 8) =
                make_float2(oacc[mt][dt][0] * inv0, oacc[mt][dt][1] * inv0);
            *reinterpret_cast<float2*>(p1 + dt * 8) =
                make_float2(oacc[mt][dt][2] * inv1, oacc[mt][dt][3] * inv1);
        }
    }
}

// ---------------------------------------------------------------------------
extern "C" void kernel_launch(void* const* d_in, const int* in_sizes, int n_in,
                              void* d_out, int out_size)
{
    const float* q    = reinterpret_cast<const float*>(d_in[0]);
    const float* k    = reinterpret_cast<const float*>(d_in[1]);
    const float* v    = reinterpret_cast<const float*>(d_in[2]);
    const int*   mask = reinterpret_cast<const int*>(d_in[3]);
    float* out = reinterpret_cast<float*>(d_out);

    cudaFuncSetAttribute(flash_mma_kernel, cudaFuncAttributeMaxDynamicSharedMemorySize, SMEM_B);

    pack_mask_kernel<<<512, 256>>>(mask);
    prep_q_kernel<<<NELEM / 4 / 256, 256>>>(reinterpret_cast<const float4*>(q));
    dim3 kvgrid(NELEM / 4 / 256, 2);
    prep_kv_kernel<<<kvgrid, 256>>>(reinterpret_cast<const float4*>(k),
                                    reinterpret_cast<const float4*>(v));

    dim3 grid(16, 64);
    flash_mma_kernel<<<grid, 128, SMEM_B>>>(out);
}